// round 16
// baseline (speedup 1.0000x reference)
#include <cuda_runtime.h>
#include <cstdint>

#define NBATCH 32
#define HDIM 56
#define WDIM 56
#define CIN 128
#define OUTC 128
#define NGRP 8
#define HC 64
#define BNC 0.9995003747f   // 1/sqrt(1+1e-3)
#define SPITCH 3140         // 56*56 + 4
#define HW 3136             // 56*56

// Scratch buffers (g-major): q,k: [b][g][hw][8]  v: [b][g][hw][16]
__device__ float g_qbuf[(size_t)NBATCH*NGRP*HW*8];
__device__ float g_kbuf[(size_t)NBATCH*NGRP*HW*8];
__device__ float g_vbuf[(size_t)NBATCH*NGRP*HW*16];

typedef unsigned long long u64;

__device__ __forceinline__ u64 pk2(float lo, float hi){
    u64 r;
    asm("mov.b64 %0, {%1, %2};" : "=l"(r) : "r"(__float_as_uint(lo)), "r"(__float_as_uint(hi)));
    return r;
}
__device__ __forceinline__ float2 upk2(u64 v){
    unsigned lo, hi;
    asm("mov.b64 {%0, %1}, %2;" : "=r"(lo), "=r"(hi) : "l"(v));
    return make_float2(__uint_as_float(lo), __uint_as_float(hi));
}
__device__ __forceinline__ u64 ffma2(u64 a, u64 b, u64 c){
    u64 d; asm("fma.rn.f32x2 %0, %1, %2, %3;" : "=l"(d) : "l"(a), "l"(b), "l"(c)); return d;
}
__device__ __forceinline__ u64 fmul2(u64 a, u64 b){
    u64 d; asm("mul.rn.f32x2 %0, %1, %2;" : "=l"(d) : "l"(a), "l"(b)); return d;
}
__device__ __forceinline__ float hadd2(u64 v){ float2 f = upk2(v); return f.x + f.y; }

// ---------------------------------------------------------------------------
// Kernel A (round-7 known-good): fused Q/K/V GEMM + BN, g-major output.
// ---------------------------------------------------------------------------
__global__ __launch_bounds__(128) void qkv_kernel(
    const float* __restrict__ x,
    const float* __restrict__ wq, const float* __restrict__ wk, const float* __restrict__ wv,
    const float* __restrict__ gq, const float* __restrict__ bq,
    const float* __restrict__ gk, const float* __restrict__ bk,
    const float* __restrict__ gv, const float* __restrict__ bv)
{
    __shared__ float XsT[16][68];   // [k][row]
    __shared__ float Ws[16][64];
    __shared__ float Ts[64][68];    // bounce tile
    const int tid = threadIdx.x;
    const int tx = tid & 15;
    const int ty = tid >> 4;
    const int row0 = blockIdx.x * 64;
    const int cb = blockIdx.y;
    const int bb = row0 / HW;
    const int hw0 = row0 - bb*HW;

    const float* wsrc; int wld, wcol0; int ch0;
    const float* gam; const float* bet;
    if (cb == 0){ wsrc=wq; wld=HC;  wcol0=0;  gam=gq; bet=bq; ch0=0; }
    else if (cb == 1){ wsrc=wk; wld=HC; wcol0=0; gam=gk; bet=bk; ch0=0; }
    else { int h=(cb-2)*64; wsrc=wv; wld=OUTC; wcol0=h; gam=gv; bet=bv; ch0=h; }

    u64 acc[8][2];
    #pragma unroll
    for (int j=0;j<8;j++){ acc[j][0]=0ULL; acc[j][1]=0ULL; }

    for (int kk=0; kk<8; kk++){
        #pragma unroll
        for (int l=0;l<8;l++){
            int idx = tid + l*128;
            int r = idx >> 4, c = idx & 15;
            XsT[c][r] = x[(size_t)(row0 + r)*CIN + kk*16 + c];
        }
        #pragma unroll
        for (int l=0;l<8;l++){
            int idx = tid + l*128;
            int r = idx >> 6, c = idx & 63;
            Ws[r][c] = wsrc[(size_t)(kk*16 + r)*wld + wcol0 + c];
        }
        __syncthreads();
        #pragma unroll
        for (int k=0;k<16;k++){
            float4 b4 = *(const float4*)&Ws[k][tx*4];
            u64 b01 = pk2(b4.x, b4.y);
            u64 b23 = pk2(b4.z, b4.w);
            float4 a0 = *(const float4*)&XsT[k][ty*8];
            float4 a1 = *(const float4*)&XsT[k][ty*8 + 4];
            float av[8] = {a0.x,a0.y,a0.z,a0.w,a1.x,a1.y,a1.z,a1.w};
            #pragma unroll
            for (int j=0;j<8;j++){
                u64 ap = pk2(av[j], av[j]);
                acc[j][0] = ffma2(ap, b01, acc[j][0]);
                acc[j][1] = ffma2(ap, b23, acc[j][1]);
            }
        }
        __syncthreads();
    }

    float sc[4], bo[4];
    #pragma unroll
    for (int c=0;c<4;c++){
        int ch = ch0 + tx*4 + c;
        sc[c] = gam[ch]*BNC;
        bo[c] = bet[ch];
    }
    #pragma unroll
    for (int j=0;j<8;j++){
        float2 f0 = upk2(acc[j][0]);
        float2 f1 = upk2(acc[j][1]);
        float4 o;
        o.x = f0.x*sc[0]+bo[0]; o.y = f0.y*sc[1]+bo[1];
        o.z = f1.x*sc[2]+bo[2]; o.w = f1.y*sc[3]+bo[3];
        *(float4*)&Ts[ty*8 + j][tx*4] = o;
    }
    __syncthreads();

    if (cb < 2){
        float* dst = (cb == 0) ? g_qbuf : g_kbuf;
        #pragma unroll
        for (int p = 0; p < 8; p++){
            int t = tid + p*128;
            int g = t >> 7;
            int r = (t >> 1) & 63;
            int half = t & 1;
            float4 val = *(const float4*)&Ts[r][g*8 + half*4];
            size_t o = (((size_t)bb*NGRP + g)*HW + hw0 + r)*8 + half*4;
            *(float4*)&dst[o] = val;
        }
    } else {
        #pragma unroll
        for (int p = 0; p < 8; p++){
            int t = tid + p*128;
            int gl = t >> 8;
            int r = (t >> 2) & 63;
            int q4 = t & 3;
            int g = (cb-2)*4 + gl;
            float4 val = *(const float4*)&Ts[r][gl*16 + q4*4];
            size_t o = (((size_t)bb*NGRP + g)*HW + hw0 + r)*16 + q4*4;
            *(float4*)&g_vbuf[o] = val;
        }
    }
}

// ---------------------------------------------------------------------------
// Kernel B v6: same tiling/smem as the 405us version but 896 threads/block:
// 2 blocks/SM -> 56 warps/SM (was 28). Phase A j-loop split over h (2x28);
// phase C threads handle 2 i x 4 ch (e-window depth 2, v dedup 4-way).
// Phase B runs on threads 0-447.
// ---------------------------------------------------------------------------
__global__ __launch_bounds__(896, 2) void attn_kernel(
    const float* __restrict__ qrel, const float* __restrict__ krel, const float* __restrict__ vrel,
    const float* __restrict__ gqk, const float* __restrict__ bqk,
    const float* __restrict__ gqr, const float* __restrict__ bqr,
    const float* __restrict__ gkr, const float* __restrict__ bkr,
    const float* __restrict__ gsv, const float* __restrict__ bsv,
    const float* __restrict__ gsve, const float* __restrict__ bsve,
    float* __restrict__ out)
{
    extern __shared__ float sm[];
    float* Ssh = sm;                   // 8*3140 = 25120 floats
    float* QRp = sm + 8*SPITCH;        // 111*12 = 1332 (phase A only)
    float* KRp = QRp + 1332;           // 1332   (phase A only)
    float* VRp = QRp;                  // 111*20 = 2220 (aliased; loaded post-A)
    float* Inv = QRp + 2220;           // 448 (aliased; written in B)

    const int it = blockIdx.x;
    const int g  = blockIdx.y;
    const int b  = blockIdx.z;
    const int tid = threadIdx.x;

    const float sqk = gqk[g]*BNC, sqr = gqr[g]*BNC, skr = gkr[g]*BNC;
    const float cbias = bqk[g] + bqr[g] + bkr[g];
    const size_t slice = ((size_t)b*NGRP + g)*HW;

    // stage QR/KR with rows padded 8 -> 12 (bank-conflict-free)
    for (int idx = tid; idx < 888; idx += 896){
        int d = idx >> 3, c = idx & 7;
        QRp[d*12 + c] = qrel[idx];
        KRp[d*12 + c] = krel[idx];
    }
    __syncthreads();

    // ---- phase A: S[ti][j][w]; j-loop split over h ----
    {
        const int h   = tid / 448;          // 0..1
        const int rem = tid - h*448;
        const int ti  = rem & 7;
        const int w   = rem >> 3;           // 0..55
        const int i   = it*8 + ti;
        const int jlo = h*28, jhi = jlo + 28;

        const ulonglong2* qp = (const ulonglong2*)&g_qbuf[(slice + i*56 + w)*8];
        ulonglong2 qA = qp[0], qB = qp[1];
        const char* kbase = (const char*)&g_kbuf[(slice + w)*8];   // j stride 1792B
        float* srow = &Ssh[ti*SPITCH + w];

        #pragma unroll 2
        for (int j = jlo; j < jhi; j++){
            const ulonglong2* kp = (const ulonglong2*)(kbase + (size_t)j*1792);
            ulonglong2 kA = kp[0], kB = kp[1];
            const ulonglong2* rp = (const ulonglong2*)&QRp[(i - j + 55)*12];
            ulonglong2 rA = rp[0], rB = rp[1];
            const ulonglong2* cp = (const ulonglong2*)&KRp[(j - i + 55)*12];
            ulonglong2 cA = cp[0], cB = cp[1];

            u64 dqk = fmul2(qA.x, kA.x); dqk = ffma2(qA.y, kA.y, dqk);
            dqk = ffma2(qB.x, kB.x, dqk); dqk = ffma2(qB.y, kB.y, dqk);
            u64 dqr = fmul2(qA.x, rA.x); dqr = ffma2(qA.y, rA.y, dqr);
            dqr = ffma2(qB.x, rB.x, dqr); dqr = ffma2(qB.y, rB.y, dqr);
            u64 dkr = fmul2(kA.x, cA.x); dkr = ffma2(kA.y, cA.y, dkr);
            dkr = ffma2(kB.x, cB.x, dkr); dkr = ffma2(kB.y, cB.y, dkr);

            srow[j*56] = hadd2(dqk)*sqk + hadd2(dqr)*sqr + hadd2(dkr)*skr + cbias;
        }
    }
    __syncthreads();

    // stage VR (rows padded 16 -> 20) into the dead QR/KR region
    for (int idx = tid; idx < 1776; idx += 896){
        int d = idx >> 4, c = idx & 15;
        VRp[d*20 + c] = vrel[idx];
    }

    // ---- phase B: softmax over w per (ti, j) row; threads 0-447 ----
    if (tid < 448){
        const int bti = tid & 7, bj = tid >> 3;
        float4* row = (float4*)&Ssh[bti*SPITCH + bj*56];
        float m = -3.4e38f;
        #pragma unroll
        for (int p = 0; p < 14; p++){
            float4 t = row[p];
            m = fmaxf(m, fmaxf(fmaxf(t.x, t.y), fmaxf(t.z, t.w)));
        }
        float s = 0.f;
        #pragma unroll
        for (int p = 0; p < 14; p++){
            float4 t = row[p];
            t.x = __expf(t.x - m); t.y = __expf(t.y - m);
            t.z = __expf(t.z - m); t.w = __expf(t.w - m);
            s += (t.x + t.y) + (t.z + t.w);
            row[p] = t;
        }
        Inv[tid] = 1.0f / s;   // Inv[bj*8 + bti]
    }
    __syncthreads();

    // ---- phase C: sv + sve over j; 2 i x 4 ch per thread; e-window depth 2 ----
    {
        const int cquad = tid & 3;
        const int iq    = (tid >> 2) & 3;
        const int wc    = tid >> 4;          // 0..55
        const int i0    = it*8 + iq*2;
        const int d0    = 55 - i0;           // e row for i0 at step j is (j + d0)

        u64 sv[2][2], se[2][2];
        #pragma unroll
        for (int p=0;p<2;p++){ sv[p][0]=0ULL; sv[p][1]=0ULL; se[p][0]=0ULL; se[p][1]=0ULL; }

        const char* vb = (const char*)&g_vbuf[(slice + wc)*16 + cquad*4];   // j stride 3584B
        const float* S0 = &Ssh[(iq*2)*SPITCH + wc];
        const float* ebase = &VRp[cquad*4];

        ulonglong2 win[2];
        win[1] = *(const ulonglong2*)(ebase + (d0-1)*20);   // row for i0+1 at j=0

        #pragma unroll 2
        for (int j = 0; j < 56; j++){
            win[j & 1] = *(const ulonglong2*)(ebase + (j + d0)*20);
            float2 iv = *(const float2*)&Inv[j*8 + iq*2];
            float p0 = S0[0*SPITCH + j*56] * iv.x;
            float p1 = S0[1*SPITCH + j*56] * iv.y;

            ulonglong2 v2 = *(const ulonglong2*)(vb + (size_t)j*3584);

            u64 P0 = pk2(p0,p0), P1 = pk2(p1,p1);
            {
                ulonglong2 e = win[j & 1];          // row j + d0      (i0)
                se[0][0]=ffma2(P0, e.x, se[0][0]); se[0][1]=ffma2(P0, e.y, se[0][1]);
            }
            {
                ulonglong2 e = win[(j-1) & 1];      // row j + d0 - 1  (i0+1)
                se[1][0]=ffma2(P1, e.x, se[1][0]); se[1][1]=ffma2(P1, e.y, se[1][1]);
            }
            sv[0][0]=ffma2(P0, v2.x, sv[0][0]); sv[0][1]=ffma2(P0, v2.y, sv[0][1]);
            sv[1][0]=ffma2(P1, v2.x, sv[1][0]); sv[1][1]=ffma2(P1, v2.y, sv[1][1]);
        }

        const int c0 = g*16 + cquad*4;
        float4 gv1 = *(const float4*)&gsv[c0];  float4 bv1 = *(const float4*)&bsv[c0];
        float4 gv2 = *(const float4*)&gsve[c0]; float4 bv2 = *(const float4*)&bsve[c0];
        #pragma unroll
        for (int ii = 0; ii < 2; ii++){
            float2 a0 = upk2(sv[ii][0]);
            float2 a1 = upk2(sv[ii][1]);
            float2 b0 = upk2(se[ii][0]);
            float2 b1 = upk2(se[ii][1]);
            float4 o;
            o.x = a0.x*gv1.x*BNC + bv1.x + b0.x*gv2.x*BNC + bv2.x;
            o.y = a0.y*gv1.y*BNC + bv1.y + b0.y*gv2.y*BNC + bv2.y;
            o.z = a1.x*gv1.z*BNC + bv1.z + b1.x*gv2.z*BNC + bv2.z;
            o.w = a1.y*gv1.w*BNC + bv1.w + b1.y*gv2.w*BNC + bv2.w;
            *(float4*)&out[((size_t)(b*HDIM + i0 + ii)*WDIM + wc)*OUTC + c0] = o;
        }
    }
}

extern "C" void kernel_launch(void* const* d_in, const int* in_sizes, int n_in,
                              void* d_out, int out_size)
{
    (void)in_sizes; (void)n_in; (void)out_size;
    const float* x    = (const float*)d_in[0];
    const float* wq   = (const float*)d_in[1];
    const float* wk   = (const float*)d_in[2];
    const float* wv   = (const float*)d_in[3];
    const float* qrel = (const float*)d_in[4];
    const float* krel = (const float*)d_in[5];
    const float* vrel = (const float*)d_in[6];
    const float* gq = (const float*)d_in[7];   const float* bq = (const float*)d_in[8];
    const float* gk = (const float*)d_in[9];   const float* bk = (const float*)d_in[10];
    const float* gv = (const float*)d_in[11];  const float* bv = (const float*)d_in[12];
    const float* gqk= (const float*)d_in[13];  const float* bqk= (const float*)d_in[14];
    const float* gqr= (const float*)d_in[15];  const float* bqr= (const float*)d_in[16];
    const float* gkr= (const float*)d_in[17];  const float* bkr= (const float*)d_in[18];
    const float* gsv= (const float*)d_in[19];  const float* bsv= (const float*)d_in[20];
    const float* gsve=(const float*)d_in[21];  const float* bsve=(const float*)d_in[22];
    float* out = (float*)d_out;

    // Ssh + max(QRp 1332 + KRp 1332, VRp 2220 + Inv 448) = Ssh + 2668 floats
    const int smem_bytes = (8*SPITCH + 2668) * (int)sizeof(float); // 111152
    cudaFuncSetAttribute(attn_kernel, cudaFuncAttributeMaxDynamicSharedMemorySize, smem_bytes);

    qkv_kernel<<<dim3(1568, 4), 128>>>(x, wq, wk, wv, gq, bq, gk, bk, gv, bv);
    attn_kernel<<<dim3(7, NGRP, NBATCH), 896, smem_bytes>>>(
        qrel, krel, vrel, gqk, bqk, gqr, bqr, gkr, bkr, gsv, bsv, gsve, bsve, out);
}

// round 17
// speedup vs baseline: 1.8670x; 1.8670x over previous
#include <cuda_runtime.h>
#include <cstdint>

#define NBATCH 32
#define HDIM 56
#define WDIM 56
#define CIN 128
#define OUTC 128
#define NGRP 8
#define HC 64
#define BNC 0.9995003747f   // 1/sqrt(1+1e-3)
#define SPITCH 3140         // 56*56 + 4
#define HW 3136             // 56*56

// Scratch buffers (g-major): q,k: [b][g][hw][8]  v: [b][g][hw][16]
__device__ float g_qbuf[(size_t)NBATCH*NGRP*HW*8];
__device__ float g_kbuf[(size_t)NBATCH*NGRP*HW*8];
__device__ float g_vbuf[(size_t)NBATCH*NGRP*HW*16];

typedef unsigned long long u64;

__device__ __forceinline__ u64 pk2(float lo, float hi){
    u64 r;
    asm("mov.b64 %0, {%1, %2};" : "=l"(r) : "r"(__float_as_uint(lo)), "r"(__float_as_uint(hi)));
    return r;
}
__device__ __forceinline__ float2 upk2(u64 v){
    unsigned lo, hi;
    asm("mov.b64 {%0, %1}, %2;" : "=r"(lo), "=r"(hi) : "l"(v));
    return make_float2(__uint_as_float(lo), __uint_as_float(hi));
}
__device__ __forceinline__ u64 ffma2(u64 a, u64 b, u64 c){
    u64 d; asm("fma.rn.f32x2 %0, %1, %2, %3;" : "=l"(d) : "l"(a), "l"(b), "l"(c)); return d;
}
__device__ __forceinline__ u64 fmul2(u64 a, u64 b){
    u64 d; asm("mul.rn.f32x2 %0, %1, %2;" : "=l"(d) : "l"(a), "l"(b)); return d;
}
__device__ __forceinline__ float hadd2(u64 v){ float2 f = upk2(v); return f.x + f.y; }

// ---------------------------------------------------------------------------
// Kernel A (round-7 known-good): fused Q/K/V GEMM + BN, g-major output.
// ---------------------------------------------------------------------------
__global__ __launch_bounds__(128) void qkv_kernel(
    const float* __restrict__ x,
    const float* __restrict__ wq, const float* __restrict__ wk, const float* __restrict__ wv,
    const float* __restrict__ gq, const float* __restrict__ bq,
    const float* __restrict__ gk, const float* __restrict__ bk,
    const float* __restrict__ gv, const float* __restrict__ bv)
{
    __shared__ float XsT[16][68];   // [k][row]
    __shared__ float Ws[16][64];
    __shared__ float Ts[64][68];    // bounce tile
    const int tid = threadIdx.x;
    const int tx = tid & 15;
    const int ty = tid >> 4;
    const int row0 = blockIdx.x * 64;
    const int cb = blockIdx.y;
    const int bb = row0 / HW;
    const int hw0 = row0 - bb*HW;

    const float* wsrc; int wld, wcol0; int ch0;
    const float* gam; const float* bet;
    if (cb == 0){ wsrc=wq; wld=HC;  wcol0=0;  gam=gq; bet=bq; ch0=0; }
    else if (cb == 1){ wsrc=wk; wld=HC; wcol0=0; gam=gk; bet=bk; ch0=0; }
    else { int h=(cb-2)*64; wsrc=wv; wld=OUTC; wcol0=h; gam=gv; bet=bv; ch0=h; }

    u64 acc[8][2];
    #pragma unroll
    for (int j=0;j<8;j++){ acc[j][0]=0ULL; acc[j][1]=0ULL; }

    for (int kk=0; kk<8; kk++){
        #pragma unroll
        for (int l=0;l<8;l++){
            int idx = tid + l*128;
            int r = idx >> 4, c = idx & 15;
            XsT[c][r] = x[(size_t)(row0 + r)*CIN + kk*16 + c];
        }
        #pragma unroll
        for (int l=0;l<8;l++){
            int idx = tid + l*128;
            int r = idx >> 6, c = idx & 63;
            Ws[r][c] = wsrc[(size_t)(kk*16 + r)*wld + wcol0 + c];
        }
        __syncthreads();
        #pragma unroll
        for (int k=0;k<16;k++){
            float4 b4 = *(const float4*)&Ws[k][tx*4];
            u64 b01 = pk2(b4.x, b4.y);
            u64 b23 = pk2(b4.z, b4.w);
            float4 a0 = *(const float4*)&XsT[k][ty*8];
            float4 a1 = *(const float4*)&XsT[k][ty*8 + 4];
            float av[8] = {a0.x,a0.y,a0.z,a0.w,a1.x,a1.y,a1.z,a1.w};
            #pragma unroll
            for (int j=0;j<8;j++){
                u64 ap = pk2(av[j], av[j]);
                acc[j][0] = ffma2(ap, b01, acc[j][0]);
                acc[j][1] = ffma2(ap, b23, acc[j][1]);
            }
        }
        __syncthreads();
    }

    float sc[4], bo[4];
    #pragma unroll
    for (int c=0;c<4;c++){
        int ch = ch0 + tx*4 + c;
        sc[c] = gam[ch]*BNC;
        bo[c] = bet[ch];
    }
    #pragma unroll
    for (int j=0;j<8;j++){
        float2 f0 = upk2(acc[j][0]);
        float2 f1 = upk2(acc[j][1]);
        float4 o;
        o.x = f0.x*sc[0]+bo[0]; o.y = f0.y*sc[1]+bo[1];
        o.z = f1.x*sc[2]+bo[2]; o.w = f1.y*sc[3]+bo[3];
        *(float4*)&Ts[ty*8 + j][tx*4] = o;
    }
    __syncthreads();

    if (cb < 2){
        float* dst = (cb == 0) ? g_qbuf : g_kbuf;
        #pragma unroll
        for (int p = 0; p < 8; p++){
            int t = tid + p*128;
            int g = t >> 7;
            int r = (t >> 1) & 63;
            int half = t & 1;
            float4 val = *(const float4*)&Ts[r][g*8 + half*4];
            size_t o = (((size_t)bb*NGRP + g)*HW + hw0 + r)*8 + half*4;
            *(float4*)&dst[o] = val;
        }
    } else {
        #pragma unroll
        for (int p = 0; p < 8; p++){
            int t = tid + p*128;
            int gl = t >> 8;
            int r = (t >> 2) & 63;
            int q4 = t & 3;
            int g = (cb-2)*4 + gl;
            float4 val = *(const float4*)&Ts[r][gl*16 + q4*4];
            size_t o = (((size_t)bb*NGRP + g)*HW + hw0 + r)*16 + q4*4;
            *(float4*)&g_vbuf[o] = val;
        }
    }
}

// ---------------------------------------------------------------------------
// Kernel B: round-15 best config (448 thr, 2 blocks/SM, pitch-12 tables,
// sliding e-window) + NEW: one-iteration software prefetch of the global
// k row (phase A) and v row (phase C) to cover L2 latency.
// ---------------------------------------------------------------------------
__global__ __launch_bounds__(448, 2) void attn_kernel(
    const float* __restrict__ qrel, const float* __restrict__ krel, const float* __restrict__ vrel,
    const float* __restrict__ gqk, const float* __restrict__ bqk,
    const float* __restrict__ gqr, const float* __restrict__ bqr,
    const float* __restrict__ gkr, const float* __restrict__ bkr,
    const float* __restrict__ gsv, const float* __restrict__ bsv,
    const float* __restrict__ gsve, const float* __restrict__ bsve,
    float* __restrict__ out)
{
    extern __shared__ float sm[];
    float* Ssh = sm;                   // 8*3140 = 25120 floats
    float* QRp = sm + 8*SPITCH;        // 111*12 = 1332 (phase A only)
    float* KRp = QRp + 1332;           // 1332   (phase A only)
    float* VRp = QRp;                  // 111*20 = 2220 (aliased; loaded post-A)
    float* Inv = QRp + 2220;           // 448 (aliased; written in B)

    const int it = blockIdx.x;
    const int g  = blockIdx.y;
    const int b  = blockIdx.z;
    const int tid = threadIdx.x;

    const float sqk = gqk[g]*BNC, sqr = gqr[g]*BNC, skr = gkr[g]*BNC;
    const float cbias = bqk[g] + bqr[g] + bkr[g];
    const size_t slice = ((size_t)b*NGRP + g)*HW;

    // stage QR/KR with rows padded 8 -> 12 (bank-conflict-free)
    for (int idx = tid; idx < 888; idx += 448){
        int d = idx >> 3, c = idx & 7;
        QRp[d*12 + c] = qrel[idx];
        KRp[d*12 + c] = krel[idx];
    }
    __syncthreads();

    // ---- phase A: S[ti][j][w]; k row software-prefetched one j ahead ----
    {
        const int ti = tid & 7;
        const int w  = tid >> 3;
        const int i  = it*8 + ti;
        const ulonglong2* qp = (const ulonglong2*)&g_qbuf[(slice + i*56 + w)*8];
        ulonglong2 qA = qp[0], qB = qp[1];
        const char* kbase = (const char*)&g_kbuf[(slice + w)*8];   // j stride 1792B
        float* srow = &Ssh[ti*SPITCH + w];

        const ulonglong2* kp0 = (const ulonglong2*)kbase;
        ulonglong2 kA = kp0[0], kB = kp0[1];

        #pragma unroll 2
        for (int j = 0; j < 56; j++){
            ulonglong2 kAn = kA, kBn = kB;
            if (j < 55){
                const ulonglong2* kp = (const ulonglong2*)(kbase + (size_t)(j+1)*1792);
                kAn = kp[0]; kBn = kp[1];
            }
            const ulonglong2* rp = (const ulonglong2*)&QRp[(i - j + 55)*12];
            ulonglong2 rA = rp[0], rB = rp[1];
            const ulonglong2* cp = (const ulonglong2*)&KRp[(j - i + 55)*12];
            ulonglong2 cA = cp[0], cB = cp[1];

            u64 dqk = fmul2(qA.x, kA.x); dqk = ffma2(qA.y, kA.y, dqk);
            dqk = ffma2(qB.x, kB.x, dqk); dqk = ffma2(qB.y, kB.y, dqk);
            u64 dqr = fmul2(qA.x, rA.x); dqr = ffma2(qA.y, rA.y, dqr);
            dqr = ffma2(qB.x, rB.x, dqr); dqr = ffma2(qB.y, rB.y, dqr);
            u64 dkr = fmul2(kA.x, cA.x); dkr = ffma2(kA.y, cA.y, dkr);
            dkr = ffma2(kB.x, cB.x, dkr); dkr = ffma2(kB.y, cB.y, dkr);

            srow[j*56] = hadd2(dqk)*sqk + hadd2(dqr)*sqr + hadd2(dkr)*skr + cbias;

            kA = kAn; kB = kBn;
        }
    }
    __syncthreads();

    // stage VR (rows padded 16 -> 20) into the dead QR/KR region
    for (int idx = tid; idx < 1776; idx += 448){
        int d = idx >> 4, c = idx & 15;
        VRp[d*20 + c] = vrel[idx];
    }

    // ---- phase B: softmax over w per (ti, j) row; e in Ssh, 1/sum in Inv ----
    {
        const int bti = tid & 7, bj = tid >> 3;
        float4* row = (float4*)&Ssh[bti*SPITCH + bj*56];
        float m = -3.4e38f;
        #pragma unroll
        for (int p = 0; p < 14; p++){
            float4 t = row[p];
            m = fmaxf(m, fmaxf(fmaxf(t.x, t.y), fmaxf(t.z, t.w)));
        }
        float s = 0.f;
        #pragma unroll
        for (int p = 0; p < 14; p++){
            float4 t = row[p];
            t.x = __expf(t.x - m); t.y = __expf(t.y - m);
            t.z = __expf(t.z - m); t.w = __expf(t.w - m);
            s += (t.x + t.y) + (t.z + t.w);
            row[p] = t;
        }
        Inv[tid] = 1.0f / s;   // Inv[bj*8 + bti]
    }
    __syncthreads();

    // ---- phase C: sv + sve over j; 4 i x 4 ch; sliding e-window; v prefetch ----
    {
        const int cquad = tid & 3;
        const int ihalf = (tid >> 2) & 1;
        const int wc    = tid >> 3;
        const int ib    = it*8 + ihalf*4;
        const int d0    = 55 - ib;

        u64 sv[4][2], se[4][2];
        #pragma unroll
        for (int p=0;p<4;p++){ sv[p][0]=0ULL; sv[p][1]=0ULL; se[p][0]=0ULL; se[p][1]=0ULL; }

        const char* vb = (const char*)&g_vbuf[(slice + wc)*16 + cquad*4];   // j stride 3584B
        const float* S0 = &Ssh[(ihalf*4)*SPITCH + wc];
        const float* ebase = &VRp[cquad*4];

        ulonglong2 win[4];
        win[1] = *(const ulonglong2*)(ebase + (d0-3)*20);
        win[2] = *(const ulonglong2*)(ebase + (d0-2)*20);
        win[3] = *(const ulonglong2*)(ebase + (d0-1)*20);

        ulonglong2 v2 = *(const ulonglong2*)vb;

        #pragma unroll 4
        for (int j = 0; j < 56; j++){
            ulonglong2 vn = v2;
            if (j < 55) vn = *(const ulonglong2*)(vb + (size_t)(j+1)*3584);

            win[j & 3] = *(const ulonglong2*)(ebase + (j + d0)*20);
            float4 iv = *(const float4*)&Inv[j*8 + ihalf*4];
            float p0 = S0[0*SPITCH + j*56] * iv.x;
            float p1 = S0[1*SPITCH + j*56] * iv.y;
            float p2 = S0[2*SPITCH + j*56] * iv.z;
            float p3 = S0[3*SPITCH + j*56] * iv.w;

            u64 P0 = pk2(p0,p0), P1 = pk2(p1,p1), P2 = pk2(p2,p2), P3 = pk2(p3,p3);
            {
                ulonglong2 e = win[j & 3];
                se[0][0]=ffma2(P0, e.x, se[0][0]); se[0][1]=ffma2(P0, e.y, se[0][1]);
            }
            {
                ulonglong2 e = win[(j-1) & 3];
                se[1][0]=ffma2(P1, e.x, se[1][0]); se[1][1]=ffma2(P1, e.y, se[1][1]);
            }
            {
                ulonglong2 e = win[(j-2) & 3];
                se[2][0]=ffma2(P2, e.x, se[2][0]); se[2][1]=ffma2(P2, e.y, se[2][1]);
            }
            {
                ulonglong2 e = win[(j-3) & 3];
                se[3][0]=ffma2(P3, e.x, se[3][0]); se[3][1]=ffma2(P3, e.y, se[3][1]);
            }
            sv[0][0]=ffma2(P0, v2.x, sv[0][0]); sv[0][1]=ffma2(P0, v2.y, sv[0][1]);
            sv[1][0]=ffma2(P1, v2.x, sv[1][0]); sv[1][1]=ffma2(P1, v2.y, sv[1][1]);
            sv[2][0]=ffma2(P2, v2.x, sv[2][0]); sv[2][1]=ffma2(P2, v2.y, sv[2][1]);
            sv[3][0]=ffma2(P3, v2.x, sv[3][0]); sv[3][1]=ffma2(P3, v2.y, sv[3][1]);

            v2 = vn;
        }

        const int c0 = g*16 + cquad*4;
        float4 gv1 = *(const float4*)&gsv[c0];  float4 bv1 = *(const float4*)&bsv[c0];
        float4 gv2 = *(const float4*)&gsve[c0]; float4 bv2 = *(const float4*)&bsve[c0];
        #pragma unroll
        for (int ii = 0; ii < 4; ii++){
            float2 a0 = upk2(sv[ii][0]);
            float2 a1 = upk2(sv[ii][1]);
            float2 b0 = upk2(se[ii][0]);
            float2 b1 = upk2(se[ii][1]);
            float4 o;
            o.x = a0.x*gv1.x*BNC + bv1.x + b0.x*gv2.x*BNC + bv2.x;
            o.y = a0.y*gv1.y*BNC + bv1.y + b0.y*gv2.y*BNC + bv2.y;
            o.z = a1.x*gv1.z*BNC + bv1.z + b1.x*gv2.z*BNC + bv2.z;
            o.w = a1.y*gv1.w*BNC + bv1.w + b1.y*gv2.w*BNC + bv2.w;
            *(float4*)&out[((size_t)(b*HDIM + ib + ii)*WDIM + wc)*OUTC + c0] = o;
        }
    }
}

extern "C" void kernel_launch(void* const* d_in, const int* in_sizes, int n_in,
                              void* d_out, int out_size)
{
    (void)in_sizes; (void)n_in; (void)out_size;
    const float* x    = (const float*)d_in[0];
    const float* wq   = (const float*)d_in[1];
    const float* wk   = (const float*)d_in[2];
    const float* wv   = (const float*)d_in[3];
    const float* qrel = (const float*)d_in[4];
    const float* krel = (const float*)d_in[5];
    const float* vrel = (const float*)d_in[6];
    const float* gq = (const float*)d_in[7];   const float* bq = (const float*)d_in[8];
    const float* gk = (const float*)d_in[9];   const float* bk = (const float*)d_in[10];
    const float* gv = (const float*)d_in[11];  const float* bv = (const float*)d_in[12];
    const float* gqk= (const float*)d_in[13];  const float* bqk= (const float*)d_in[14];
    const float* gqr= (const float*)d_in[15];  const float* bqr= (const float*)d_in[16];
    const float* gkr= (const float*)d_in[17];  const float* bkr= (const float*)d_in[18];
    const float* gsv= (const float*)d_in[19];  const float* bsv= (const float*)d_in[20];
    const float* gsve=(const float*)d_in[21];  const float* bsve=(const float*)d_in[22];
    float* out = (float*)d_out;

    // Ssh + max(QRp 1332 + KRp 1332, VRp 2220 + Inv 448) = Ssh + 2668 floats
    const int smem_bytes = (8*SPITCH + 2668) * (int)sizeof(float); // 111152
    cudaFuncSetAttribute(attn_kernel, cudaFuncAttributeMaxDynamicSharedMemorySize, smem_bytes);

    qkv_kernel<<<dim3(1568, 4), 128>>>(x, wq, wk, wv, gq, bq, gk, bk, gv, bv);
    attn_kernel<<<dim3(7, NGRP, NBATCH), 448, smem_bytes>>>(
        qrel, krel, vrel, gqk, bqk, gqr, bqr, gkr, bkr, gsv, bsv, gsve, bsve, out);
}